// round 13
// baseline (speedup 1.0000x reference)
#include <cuda_runtime.h>
#include <cuda_fp16.h>
#include <cstdint>
#include <math.h>

// ---------------------------------------------------------------------------
// Problem constants
// ---------------------------------------------------------------------------
#define BATCH 8
#define WDIM 64
#define CC 512
#define C8 64
#define C2 256
#define NPIX 4096
#define NPOOL 1024
#define NCAT 384

// ---------------------------------------------------------------------------
// Scratch (device globals; allocation-free)
// ---------------------------------------------------------------------------
__device__ __half d_Xh[(long long)BATCH * NPIX * CC];     // 32 MB  x fp16
__device__ __half d_WcatT[NCAT * CC];                     // [384][512]
__device__ __half d_WoT[CC * C2];                         // [512][256]
__device__ __half d_Gh[(long long)BATCH * NPIX * C8];     // 4 MB   g full-res
__device__ __half d_Fh[BATCH * NPOOL * C8];               // 1 MB   pooled f [p][c]
__device__ __half d_Vth[BATCH * C2 * NPOOL];              // 4 MB   pooled h transposed [d][p]
__device__ __half d_Oh[(long long)BATCH * NPIX * C2];     // 16 MB  attention out

// ---------------------------------------------------------------------------
// Helpers
// ---------------------------------------------------------------------------
__device__ __forceinline__ uint32_t smem_u32(const void* p) {
    uint32_t a;
    asm("{ .reg .u64 t; cvta.to.shared.u64 t, %1; cvt.u32.u64 %0, t; }" : "=r"(a) : "l"(p));
    return a;
}
__device__ __forceinline__ void cp16(uint32_t dst, const void* src) {
    asm volatile("cp.async.cg.shared.global [%0], [%1], 16;" ::"r"(dst), "l"(src));
}
#define CP_COMMIT() asm volatile("cp.async.commit_group;" ::: "memory")
#define CP_WAIT0()  asm volatile("cp.async.wait_group 0;" ::: "memory")
#define CP_WAIT1()  asm volatile("cp.async.wait_group 1;" ::: "memory")

__device__ __forceinline__ void mma_f16(float* d, const uint32_t* a, const uint32_t* b) {
    asm volatile(
        "mma.sync.aligned.m16n8k16.row.col.f32.f16.f16.f32 "
        "{%0,%1,%2,%3}, {%4,%5,%6,%7}, {%8,%9}, {%0,%1,%2,%3};"
        : "+f"(d[0]), "+f"(d[1]), "+f"(d[2]), "+f"(d[3])
        : "r"(a[0]), "r"(a[1]), "r"(a[2]), "r"(a[3]), "r"(b[0]), "r"(b[1]));
}
__device__ __forceinline__ void ldsm4(uint32_t* r, uint32_t a) {
    asm volatile("ldmatrix.sync.aligned.m8n8.x4.shared.b16 {%0,%1,%2,%3}, [%4];"
                 : "=r"(r[0]), "=r"(r[1]), "=r"(r[2]), "=r"(r[3]) : "r"(a));
}
__device__ __forceinline__ uint32_t pack2(float x, float y) {
    __half2 h = __floats2half2_rn(x, y);
    return *reinterpret_cast<uint32_t*>(&h);
}
__device__ __forceinline__ uint32_t ex2_h2(uint32_t in) {
    uint32_t r;
    asm("ex2.approx.f16x2 %0, %1;" : "=r"(r) : "r"(in));
    return r;
}
__device__ __forceinline__ float h2sum(uint32_t u) {
    __half2 h = *reinterpret_cast<__half2*>(&u);
    return __low2float(h) + __high2float(h);
}
#define L2E 1.4426950408889634f

// ---------------------------------------------------------------------------
// Shared GEMM config: CTA 256x64, BK=32 halfs, 8 warps (4m x 2n), 3 stages.
// ---------------------------------------------------------------------------
#define HSTR 40
#define HASTG (256 * HSTR * 2)
#define HBSTG (64 * HSTR * 2)
#define HGSTG (HASTG + HBSTG)
#define SMEM_TOTAL_G (3 * HGSTG)

// ---------------------------------------------------------------------------
// Projection GEMM + fused 2x2 max-pool epilogue.
// ---------------------------------------------------------------------------
#define CSTR 72

__global__ void __launch_bounds__(256, 2) gemm_proj()
{
    extern __shared__ __align__(16) char smem[];
    const int m0 = blockIdx.y * 256;
    const int n0 = blockIdx.x * 64;
    const int tid = threadIdx.x;
    const int wid = tid >> 5, lane = tid & 31;
    const int gid = lane >> 2, tig = lane & 3;
    const int wm = (wid & 3) * 64;
    const int wn = (wid >> 2) * 32;

    const __half* A = d_Xh;
    const __half* Bt = d_WcatT;
    const uint32_t sb = smem_u32(smem);
    const int KT = CC / 32;

    const int arow = lane & 15;
    const int acol = (lane >> 4) << 4;
    const int brow = (lane & 7) + ((lane >> 4) & 1) * 8;
    const int bcol = ((lane >> 3) & 1) << 4;
    uint32_t aoff[4], boff[2];
#pragma unroll
    for (int mt = 0; mt < 4; mt++) aoff[mt] = (uint32_t)((wm + mt * 16 + arow) * 80 + acol);
#pragma unroll
    for (int p = 0; p < 2; p++) boff[p] = (uint32_t)(HASTG + (wn + p * 16 + brow) * 80 + bcol);

    auto issue = [&](int kt, int s) {
        const uint32_t aB = sb + (uint32_t)(s * HGSTG);
        const uint32_t bB = aB + HASTG;
#pragma unroll
        for (int it = 0; it < 4; it++) {
            int idx = tid + it * 256;
            int r = idx >> 2, q = idx & 3;
            cp16(aB + (uint32_t)(r * 80 + q * 16),
                 A + (long long)(m0 + r) * CC + kt * 32 + q * 8);
        }
        {
            int r = tid >> 2, q = tid & 3;
            cp16(bB + (uint32_t)(r * 80 + q * 16),
                 Bt + (long long)(n0 + r) * CC + kt * 32 + q * 8);
        }
        CP_COMMIT();
    };

    float acc[4][4][4];
#pragma unroll
    for (int i = 0; i < 4; i++)
#pragma unroll
        for (int j = 0; j < 4; j++)
#pragma unroll
            for (int k = 0; k < 4; k++) acc[i][j][k] = 0.f;

    issue(0, 0);
    issue(1, 1);

    for (int kt = 0; kt < KT; kt++) {
        const int s = kt % 3;
        if (kt < KT - 1) CP_WAIT1(); else CP_WAIT0();
        __syncthreads();
        if (kt + 2 < KT) issue(kt + 2, (kt + 2) % 3);

        const uint32_t stB = sb + (uint32_t)(s * HGSTG);
#pragma unroll
        for (int ks = 0; ks < 2; ks++) {
            uint32_t a[4][4], b[4][2];
#pragma unroll
            for (int mt = 0; mt < 4; mt++) ldsm4(a[mt], stB + aoff[mt] + ks * 32);
#pragma unroll
            for (int p = 0; p < 2; p++) {
                uint32_t t[4];
                ldsm4(t, stB + boff[p] + ks * 32);
                b[2 * p][0] = t[0]; b[2 * p][1] = t[1];
                b[2 * p + 1][0] = t[2]; b[2 * p + 1][1] = t[3];
            }
#pragma unroll
            for (int mt = 0; mt < 4; mt++)
#pragma unroll
                for (int nt = 0; nt < 4; nt++)
                    mma_f16(acc[mt][nt], a[mt], b[nt]);
        }
    }

    __syncthreads();
    uint32_t* Cw = (uint32_t*)smem;
#pragma unroll
    for (int mt = 0; mt < 4; mt++)
#pragma unroll
        for (int h = 0; h < 2; h++) {
            int row = wm + mt * 16 + gid + h * 8;
#pragma unroll
            for (int nt = 0; nt < 4; nt++)
                Cw[row * (CSTR / 2) + wn / 2 + nt * 4 + tig] =
                    pack2(acc[mt][nt][h * 2], acc[mt][nt][h * 2 + 1]);
        }
    __syncthreads();

    const __half* Cs = (const __half*)smem;
    const int b = m0 >> 12;
    const int pix0 = m0 & 4095;
    const int pr0 = pix0 >> 7;

    if (n0 == 64) {
        __half* G = d_Gh + (long long)m0 * C8;
#pragma unroll
        for (int it = 0; it < 8; it++) {
            int idx = tid + it * 256;
            int row = idx >> 3, q = idx & 7;
            uint4 v = *reinterpret_cast<const uint4*>(&Cw[row * (CSTR / 2) + q * 4]);
            *reinterpret_cast<uint4*>(&G[row * C8 + q * 8]) = v;
        }
    } else if (n0 == 0) {
        __half* F = d_Fh + (b * NPOOL + pr0 * 32) * C8;
        const __half2* C2s = (const __half2*)Cs;
#pragma unroll
        for (int it = 0; it < 8; it++) {
            int idx = tid + it * 256;
            int p = idx >> 5, c2 = idx & 31;
            int base = ((p >> 5) * 2) * 64 + (p & 31) * 2;
            __half2 v0 = C2s[(base) * (CSTR / 2) + c2];
            __half2 v1 = C2s[(base + 1) * (CSTR / 2) + c2];
            __half2 v2 = C2s[(base + 64) * (CSTR / 2) + c2];
            __half2 v3 = C2s[(base + 65) * (CSTR / 2) + c2];
            __half2 v = __hmax2(__hmax2(v0, v1), __hmax2(v2, v3));
            *reinterpret_cast<__half2*>(&F[p * C8 + 2 * c2]) = v;
        }
    } else {
        int c = tid & 63;
        int pgrp = tid >> 6;
        int d = n0 - 128 + c;
        __half buf[16];
#pragma unroll
        for (int j = 0; j < 16; j++) {
            int p = pgrp * 16 + j;
            int base = ((p >> 5) * 2) * 64 + (p & 31) * 2;
            __half v0 = Cs[(base) * CSTR + c];
            __half v1 = Cs[(base + 1) * CSTR + c];
            __half v2 = Cs[(base + 64) * CSTR + c];
            __half v3 = Cs[(base + 65) * CSTR + c];
            buf[j] = __hmax(__hmax(v0, v1), __hmax(v2, v3));
        }
        __half* dst = d_Vth + ((long long)b * C2 + d) * NPOOL + pr0 * 32 + pgrp * 16;
        *reinterpret_cast<uint4*>(dst) = *reinterpret_cast<uint4*>(buf);
        *reinterpret_cast<uint4*>(dst + 8) = *reinterpret_cast<uint4*>(buf + 8);
    }
}

// ---------------------------------------------------------------------------
// Output GEMM: out = gamma * (Oh @ WoT^T) + x   (M=32768, N=512, K=256)
// ---------------------------------------------------------------------------
__global__ void __launch_bounds__(256, 2) gemm_out(
    const float* __restrict__ resid, const float* __restrict__ gamma,
    float* __restrict__ C)
{
    extern __shared__ __align__(16) char smem[];
    const int m0 = blockIdx.y * 256;
    const int n0 = blockIdx.x * 64;
    const int tid = threadIdx.x;
    const int wid = tid >> 5, lane = tid & 31;
    const int gid = lane >> 2, tig = lane & 3;
    const int wm = (wid & 3) * 64;
    const int wn = (wid >> 2) * 32;

    const __half* A = d_Oh;
    const __half* Bt = d_WoT;
    const uint32_t sb = smem_u32(smem);
    const int KT = C2 / 32;

    const int arow = lane & 15;
    const int acol = (lane >> 4) << 4;
    const int brow = (lane & 7) + ((lane >> 4) & 1) * 8;
    const int bcol = ((lane >> 3) & 1) << 4;
    uint32_t aoff[4], boff[2];
#pragma unroll
    for (int mt = 0; mt < 4; mt++) aoff[mt] = (uint32_t)((wm + mt * 16 + arow) * 80 + acol);
#pragma unroll
    for (int p = 0; p < 2; p++) boff[p] = (uint32_t)(HASTG + (wn + p * 16 + brow) * 80 + bcol);

    auto issue = [&](int kt, int s) {
        const uint32_t aB = sb + (uint32_t)(s * HGSTG);
        const uint32_t bB = aB + HASTG;
#pragma unroll
        for (int it = 0; it < 4; it++) {
            int idx = tid + it * 256;
            int r = idx >> 2, q = idx & 3;
            cp16(aB + (uint32_t)(r * 80 + q * 16),
                 A + (long long)(m0 + r) * C2 + kt * 32 + q * 8);
        }
        {
            int r = tid >> 2, q = tid & 3;
            cp16(bB + (uint32_t)(r * 80 + q * 16),
                 Bt + (long long)(n0 + r) * C2 + kt * 32 + q * 8);
        }
        CP_COMMIT();
    };

    float acc[4][4][4];
#pragma unroll
    for (int i = 0; i < 4; i++)
#pragma unroll
        for (int j = 0; j < 4; j++)
#pragma unroll
            for (int k = 0; k < 4; k++) acc[i][j][k] = 0.f;

    issue(0, 0);
    issue(1, 1);

    for (int kt = 0; kt < KT; kt++) {
        const int s = kt % 3;
        if (kt < KT - 1) CP_WAIT1(); else CP_WAIT0();
        __syncthreads();
        if (kt + 2 < KT) issue(kt + 2, (kt + 2) % 3);

        const uint32_t stB = sb + (uint32_t)(s * HGSTG);
#pragma unroll
        for (int ks = 0; ks < 2; ks++) {
            uint32_t a[4][4], b[4][2];
#pragma unroll
            for (int mt = 0; mt < 4; mt++) ldsm4(a[mt], stB + aoff[mt] + ks * 32);
#pragma unroll
            for (int p = 0; p < 2; p++) {
                uint32_t t[4];
                ldsm4(t, stB + boff[p] + ks * 32);
                b[2 * p][0] = t[0]; b[2 * p][1] = t[1];
                b[2 * p + 1][0] = t[2]; b[2 * p + 1][1] = t[3];
            }
#pragma unroll
            for (int mt = 0; mt < 4; mt++)
#pragma unroll
                for (int nt = 0; nt < 4; nt++)
                    mma_f16(acc[mt][nt], a[mt], b[nt]);
        }
    }

    const float gm = gamma[0];
#pragma unroll
    for (int mt = 0; mt < 4; mt++)
#pragma unroll
        for (int h = 0; h < 2; h++) {
            long long row = m0 + wm + mt * 16 + gid + h * 8;
#pragma unroll
            for (int nt = 0; nt < 4; nt++) {
                long long off = row * CC + n0 + wn + nt * 8 + 2 * tig;
                float2 rv = *reinterpret_cast<const float2*>(&resid[off]);
                float2 v;
                v.x = fmaf(gm, acc[mt][nt][h * 2], rv.x);
                v.y = fmaf(gm, acc[mt][nt][h * 2 + 1], rv.y);
                *reinterpret_cast<float2*>(&C[off]) = v;
            }
        }
}

// ---------------------------------------------------------------------------
// Flash attention (FA2-style): 256 thr / 64 q, 2 CTAs/SM, 16 chunks of 64.
// Each warp: 16 rows x ALL 64 keys of S (S duplicated across the 2 PV
// col-groups). Stats warp-local (shuffles). P stays in registers: S-acc
// fragment layout == PV A-operand layout. 1 cp-wait + 1 barrier per chunk.
// Smem/CTA = 99 KB: Q 9K | K 2x9K | V 2x36K.
// ---------------------------------------------------------------------------
#define FQ 64
#define NCHUNK 16
#define SM_Q 0
#define SM_K 9216
#define SM_V 27648
#define FLASH_SMEM 101376

__global__ void __launch_bounds__(256, 2) flash_h()
{
    extern __shared__ __align__(16) char fsm[];
    const uint32_t sb = smem_u32(fsm);

    const int b = blockIdx.y;
    const int q0 = blockIdx.x * FQ;
    const __half* Qg = d_Gh + ((long long)b * NPIX + q0) * C8;
    const __half* Fb = d_Fh + b * NPOOL * C8;
    const __half* Vtb = d_Vth + (long long)b * C2 * NPOOL;
    __half* Ob = d_Oh + (long long)b * NPIX * C2;

    const int tid = threadIdx.x;
    const int wid = tid >> 5, lane = tid & 31;
    const int gid = lane >> 2, tig = lane & 3;
    const int wm = (wid & 3) * 16;     // 4 row-groups x 16 rows
    const int wgrp = wid >> 2;         // 2 PV col-groups
    const int wnP = wgrp * 128;

    const int arow = lane & 15;
    const int acol = (lane >> 4) << 4;
    const int brow = (lane & 7) + ((lane >> 4) & 1) * 8;
    const int bcol = ((lane >> 3) & 1) << 4;
    const uint32_t qoff = (uint32_t)(SM_Q + (wm + arow) * 144 + acol);
    uint32_t koff[4], voff[8];
#pragma unroll
    for (int j = 0; j < 4; j++)
        koff[j] = (uint32_t)(SM_K + (j * 16 + brow) * 144 + bcol);
#pragma unroll
    for (int p = 0; p < 8; p++)
        voff[p] = (uint32_t)(SM_V + (wnP + p * 16 + brow) * 144 + bcol);

    // K(c)+V(c) -> buffer c&1, one commit group
    auto issueKV = [&](int c) {
        const uint32_t kb = sb + SM_K + (uint32_t)((c & 1) * 9216);
        const uint32_t vb = sb + SM_V + (uint32_t)((c & 1) * 36864);
#pragma unroll
        for (int it = 0; it < 2; it++) {
            int idx = tid + it * 256;
            int r = idx >> 3, q = idx & 7;
            cp16(kb + (uint32_t)(r * 144 + q * 16),
                 Fb + (c * 64 + r) * C8 + q * 8);
        }
#pragma unroll
        for (int it = 0; it < 8; it++) {
            int idx = tid + it * 256;
            int r = idx >> 3, q = idx & 7;
            cp16(vb + (uint32_t)(r * 144 + q * 16),
                 Vtb + (long long)r * NPOOL + c * 64 + q * 8);
        }
        CP_COMMIT();
    };

    // prologue: Q + K0 + V0, one group
    {
#pragma unroll
        for (int it = 0; it < 2; it++) {
            int idx = tid + it * 256;
            int r = idx >> 3, q = idx & 7;
            cp16(sb + SM_Q + (uint32_t)(r * 144 + q * 16),
                 Qg + (long long)r * C8 + q * 8);
        }
        issueKV(0);
    }
    CP_WAIT0();
    __syncthreads();
    uint32_t qf[4][4];
#pragma unroll
    for (int ks = 0; ks < 4; ks++) ldsm4(qf[ks], sb + qoff + ks * 32);

    float accO[16][4];
#pragma unroll
    for (int n = 0; n < 16; n++)
#pragma unroll
        for (int k = 0; k < 4; k++) accO[n][k] = 0.f;
    float mM[2] = {-1e30f, -1e30f};
    float lL[2] = {0.f, 0.f};

    for (int c = 0; c < NCHUNK; c++) {
        const uint32_t sK = (uint32_t)((c & 1) * 9216);
        const uint32_t sV = (uint32_t)((c & 1) * 36864);

        if (c) {
            CP_WAIT0();                // K(c)+V(c) landed
            __syncthreads();           // also guarantees buf c+1&1 fully consumed
        }
        if (c + 1 < NCHUNK) issueKV(c + 1);

        // ---- S = Q @ F^T : 16 rows x 64 keys per warp (8 n8-tiles) ----
        float accS[8][4];
#pragma unroll
        for (int n = 0; n < 8; n++)
#pragma unroll
            for (int k = 0; k < 4; k++) accS[n][k] = 0.f;
#pragma unroll
        for (int ks = 0; ks < 4; ks++) {
#pragma unroll
            for (int j = 0; j < 4; j++) {
                uint32_t t[4], b0[2], b1[2];
                ldsm4(t, sb + sK + koff[j] + ks * 32);
                b0[0] = t[0]; b0[1] = t[1];
                b1[0] = t[2]; b1[1] = t[3];
                mma_f16(accS[2 * j], qf[ks], b0);
                mma_f16(accS[2 * j + 1], qf[ks], b1);
            }
        }

        // ---- warp-local row max over all 64 keys ----
        float cl = -1e30f, ch = -1e30f;
#pragma unroll
        for (int nt = 0; nt < 8; nt++) {
            cl = fmaxf(cl, fmaxf(accS[nt][0], accS[nt][1]));
            ch = fmaxf(ch, fmaxf(accS[nt][2], accS[nt][3]));
        }
#pragma unroll
        for (int o = 1; o <= 2; o <<= 1) {
            cl = fmaxf(cl, __shfl_xor_sync(0xffffffffu, cl, o));
            ch = fmaxf(ch, __shfl_xor_sync(0xffffffffu, ch, o));
        }
        float sc[2], nm[2];
        {
            float mn0 = fmaxf(mM[0], cl);
            float mn1 = fmaxf(mM[1], ch);
            sc[0] = __expf(mM[0] - mn0);
            sc[1] = __expf(mM[1] - mn1);
            mM[0] = mn0;
            mM[1] = mn1;
            nm[0] = -mn0 * L2E;
            nm[1] = -mn1 * L2E;
        }

        // ---- P in registers: exp via ex2.f16x2, forms PV A fragments ----
        uint32_t pf[4][4];
        float ps[2] = {0.f, 0.f};
#pragma unroll
        for (int ks = 0; ks < 4; ks++) {
            pf[ks][0] = ex2_h2(pack2(fmaf(accS[2 * ks][0], L2E, nm[0]),
                                     fmaf(accS[2 * ks][1], L2E, nm[0])));
            pf[ks][1] = ex2_h2(pack2(fmaf(accS[2 * ks][2], L2E, nm[1]),
                                     fmaf(accS[2 * ks][3], L2E, nm[1])));
            pf[ks][2] = ex2_h2(pack2(fmaf(accS[2 * ks + 1][0], L2E, nm[0]),
                                     fmaf(accS[2 * ks + 1][1], L2E, nm[0])));
            pf[ks][3] = ex2_h2(pack2(fmaf(accS[2 * ks + 1][2], L2E, nm[1]),
                                     fmaf(accS[2 * ks + 1][3], L2E, nm[1])));
            ps[0] += h2sum(pf[ks][0]) + h2sum(pf[ks][2]);
            ps[1] += h2sum(pf[ks][1]) + h2sum(pf[ks][3]);
        }
#pragma unroll
        for (int o = 1; o <= 2; o <<= 1) {
            ps[0] += __shfl_xor_sync(0xffffffffu, ps[0], o);
            ps[1] += __shfl_xor_sync(0xffffffffu, ps[1], o);
        }
        lL[0] = lL[0] * sc[0] + ps[0];
        lL[1] = lL[1] * sc[1] + ps[1];

        // ---- rescale accO ----
#pragma unroll
        for (int nt = 0; nt < 16; nt++) {
            accO[nt][0] *= sc[0];
            accO[nt][1] *= sc[0];
            accO[nt][2] *= sc[1];
            accO[nt][3] *= sc[1];
        }

        // ---- O += P @ V (P from registers) ----
#pragma unroll
        for (int ks = 0; ks < 4; ks++) {
#pragma unroll
            for (int p = 0; p < 8; p++) {
                uint32_t t[4], b0[2], b1[2];
                ldsm4(t, sb + sV + voff[p] + ks * 32);
                b0[0] = t[0]; b0[1] = t[1];
                b1[0] = t[2]; b1[1] = t[3];
                mma_f16(accO[2 * p], pf[ks], b0);
                mma_f16(accO[2 * p + 1], pf[ks], b1);
            }
        }
    }

    // ---- finalize ----
    {
        float il = 1.f / lL[0], ih = 1.f / lL[1];
        int row = q0 + wm + gid;
#pragma unroll
        for (int nt = 0; nt < 16; nt++) {
            int col = wnP + nt * 8 + 2 * tig;
            *reinterpret_cast<uint32_t*>(&Ob[(long long)row * C2 + col]) =
                pack2(accO[nt][0] * il, accO[nt][1] * il);
            *reinterpret_cast<uint32_t*>(&Ob[(long long)(row + 8) * C2 + col]) =
                pack2(accO[nt][2] * ih, accO[nt][3] * ih);
        }
    }
}

// ---------------------------------------------------------------------------
// x -> fp16
// ---------------------------------------------------------------------------
__global__ void convert_x_kernel(const float* __restrict__ x)
{
    int idx = blockIdx.x * blockDim.x + threadIdx.x;
    const float4 v = reinterpret_cast<const float4*>(x)[idx];
    uint2 u;
    u.x = pack2(v.x, v.y);
    u.y = pack2(v.z, v.w);
    reinterpret_cast<uint2*>(d_Xh)[idx] = u;
}

// ---------------------------------------------------------------------------
// Weights: WcatT [384][512] fp16, WoT [512][256] fp16
// ---------------------------------------------------------------------------
__global__ void concat_w_kernel(const float* __restrict__ wf,
                                const float* __restrict__ wg,
                                const float* __restrict__ wh,
                                const float* __restrict__ wo)
{
    int idx = blockIdx.x * blockDim.x + threadIdx.x;
    const int n1 = NCAT * CC;
    if (idx < n1) {
        int j = idx / CC, k = idx % CC;
        float v;
        if (j < 64)       v = wf[k * C8 + j];
        else if (j < 128) v = wg[k * C8 + (j - 64)];
        else              v = wh[k * C2 + (j - 128)];
        d_WcatT[idx] = __float2half_rn(v);
    } else if (idx < n1 + CC * C2) {
        int i2 = idx - n1;
        int c = i2 / C2, d = i2 % C2;
        d_WoT[i2] = __float2half_rn(wo[d * CC + c]);
    }
}

// ---------------------------------------------------------------------------
// Launch
// ---------------------------------------------------------------------------
extern "C" void kernel_launch(void* const* d_in, const int* in_sizes, int n_in,
                              void* d_out, int out_size)
{
    const float* x     = (const float*)d_in[0];
    const float* wf    = (const float*)d_in[1];
    const float* wg    = (const float*)d_in[2];
    const float* wh    = (const float*)d_in[3];
    const float* wo    = (const float*)d_in[4];
    const float* gamma = (const float*)d_in[5];
    float* out = (float*)d_out;

    cudaFuncSetAttribute(gemm_proj,
                         cudaFuncAttributeMaxDynamicSharedMemorySize, SMEM_TOTAL_G);
    cudaFuncSetAttribute(gemm_out,
                         cudaFuncAttributeMaxDynamicSharedMemorySize, SMEM_TOTAL_G);
    cudaFuncSetAttribute(flash_h,
                         cudaFuncAttributeMaxDynamicSharedMemorySize, FLASH_SMEM);

    // 0) x -> fp16
    convert_x_kernel<<<(BATCH * NPIX * CC / 4 + 255) / 256, 256>>>(x);

    // 1) weights -> fp16 transposed
    concat_w_kernel<<<(NCAT * CC + CC * C2 + 255) / 256, 256>>>(wf, wg, wh, wo);

    // 2+3) projection GEMM with fused pooling epilogue
    gemm_proj<<<dim3(NCAT / 64, (BATCH * NPIX) / 256), 256, SMEM_TOTAL_G>>>();

    // 4-6) fused attention -> Oh fp16
    flash_h<<<dim3(NPIX / FQ, BATCH), 256, FLASH_SMEM>>>();

    // 7) out = gamma * (Oh @ wo) + x
    gemm_out<<<dim3(CC / 64, (BATCH * NPIX) / 256), 256, SMEM_TOTAL_G>>>(x, gamma, out);
}

// round 14
// speedup vs baseline: 1.0461x; 1.0461x over previous
#include <cuda_runtime.h>
#include <cuda_fp16.h>
#include <cstdint>
#include <math.h>

// ---------------------------------------------------------------------------
// Problem constants
// ---------------------------------------------------------------------------
#define BATCH 8
#define WDIM 64
#define CC 512
#define C8 64
#define C2 256
#define NPIX 4096
#define NPOOL 1024
#define NCAT 384

// ---------------------------------------------------------------------------
// Scratch (device globals; allocation-free)
// ---------------------------------------------------------------------------
__device__ __half d_Xh[(long long)BATCH * NPIX * CC];     // 32 MB  x fp16
__device__ __half d_WcatT[NCAT * CC];                     // [384][512]
__device__ __half d_WoT[CC * C2];                         // [512][256]
__device__ __half d_Gh[(long long)BATCH * NPIX * C8];     // 4 MB   g full-res
__device__ __half d_Fh[BATCH * NPOOL * C8];               // 1 MB   pooled f [p][c]
__device__ __half d_Vth[BATCH * C2 * NPOOL];              // 4 MB   pooled h transposed [d][p]
__device__ __half d_Oh[(long long)BATCH * NPIX * C2];     // 16 MB  attention out

// ---------------------------------------------------------------------------
// Helpers
// ---------------------------------------------------------------------------
__device__ __forceinline__ uint32_t smem_u32(const void* p) {
    uint32_t a;
    asm("{ .reg .u64 t; cvta.to.shared.u64 t, %1; cvt.u32.u64 %0, t; }" : "=r"(a) : "l"(p));
    return a;
}
__device__ __forceinline__ void cp16(uint32_t dst, const void* src) {
    asm volatile("cp.async.cg.shared.global [%0], [%1], 16;" ::"r"(dst), "l"(src));
}
#define CP_COMMIT() asm volatile("cp.async.commit_group;" ::: "memory")
#define CP_WAIT0()  asm volatile("cp.async.wait_group 0;" ::: "memory")
#define CP_WAIT1()  asm volatile("cp.async.wait_group 1;" ::: "memory")

__device__ __forceinline__ void bar_sync(int id, int cnt) {
    asm volatile("bar.sync %0, %1;" ::"r"(id), "r"(cnt) : "memory");
}
__device__ __forceinline__ void bar_arrive(int id, int cnt) {
    asm volatile("bar.arrive %0, %1;" ::"r"(id), "r"(cnt) : "memory");
}
#define MEMBAR_CTA() asm volatile("membar.cta;" ::: "memory")

__device__ __forceinline__ void mma_f16(float* d, const uint32_t* a, const uint32_t* b) {
    asm volatile(
        "mma.sync.aligned.m16n8k16.row.col.f32.f16.f16.f32 "
        "{%0,%1,%2,%3}, {%4,%5,%6,%7}, {%8,%9}, {%0,%1,%2,%3};"
        : "+f"(d[0]), "+f"(d[1]), "+f"(d[2]), "+f"(d[3])
        : "r"(a[0]), "r"(a[1]), "r"(a[2]), "r"(a[3]), "r"(b[0]), "r"(b[1]));
}
__device__ __forceinline__ void ldsm4(uint32_t* r, uint32_t a) {
    asm volatile("ldmatrix.sync.aligned.m8n8.x4.shared.b16 {%0,%1,%2,%3}, [%4];"
                 : "=r"(r[0]), "=r"(r[1]), "=r"(r[2]), "=r"(r[3]) : "r"(a));
}
__device__ __forceinline__ uint32_t pack2(float x, float y) {
    __half2 h = __floats2half2_rn(x, y);
    return *reinterpret_cast<uint32_t*>(&h);
}
__device__ __forceinline__ uint32_t ex2_h2(uint32_t in) {
    uint32_t r;
    asm("ex2.approx.f16x2 %0, %1;" : "=r"(r) : "r"(in));
    return r;
}
__device__ __forceinline__ float h2sum(uint32_t u) {
    __half2 h = *reinterpret_cast<__half2*>(&u);
    return __low2float(h) + __high2float(h);
}
#define L2E 1.4426950408889634f

// ---------------------------------------------------------------------------
// Shared GEMM config: CTA 256x64, BK=32 halfs, 8 warps (4m x 2n), 3 stages.
// ---------------------------------------------------------------------------
#define HSTR 40
#define HASTG (256 * HSTR * 2)
#define HBSTG (64 * HSTR * 2)
#define HGSTG (HASTG + HBSTG)
#define SMEM_TOTAL_G (3 * HGSTG)

// ---------------------------------------------------------------------------
// Projection GEMM + fused 2x2 max-pool epilogue.
// ---------------------------------------------------------------------------
#define CSTR 72

__global__ void __launch_bounds__(256, 2) gemm_proj()
{
    extern __shared__ __align__(16) char smem[];
    const int m0 = blockIdx.y * 256;
    const int n0 = blockIdx.x * 64;
    const int tid = threadIdx.x;
    const int wid = tid >> 5, lane = tid & 31;
    const int gid = lane >> 2, tig = lane & 3;
    const int wm = (wid & 3) * 64;
    const int wn = (wid >> 2) * 32;

    const __half* A = d_Xh;
    const __half* Bt = d_WcatT;
    const uint32_t sb = smem_u32(smem);
    const int KT = CC / 32;

    const int arow = lane & 15;
    const int acol = (lane >> 4) << 4;
    const int brow = (lane & 7) + ((lane >> 4) & 1) * 8;
    const int bcol = ((lane >> 3) & 1) << 4;
    uint32_t aoff[4], boff[2];
#pragma unroll
    for (int mt = 0; mt < 4; mt++) aoff[mt] = (uint32_t)((wm + mt * 16 + arow) * 80 + acol);
#pragma unroll
    for (int p = 0; p < 2; p++) boff[p] = (uint32_t)(HASTG + (wn + p * 16 + brow) * 80 + bcol);

    auto issue = [&](int kt, int s) {
        const uint32_t aB = sb + (uint32_t)(s * HGSTG);
        const uint32_t bB = aB + HASTG;
#pragma unroll
        for (int it = 0; it < 4; it++) {
            int idx = tid + it * 256;
            int r = idx >> 2, q = idx & 3;
            cp16(aB + (uint32_t)(r * 80 + q * 16),
                 A + (long long)(m0 + r) * CC + kt * 32 + q * 8);
        }
        {
            int r = tid >> 2, q = tid & 3;
            cp16(bB + (uint32_t)(r * 80 + q * 16),
                 Bt + (long long)(n0 + r) * CC + kt * 32 + q * 8);
        }
        CP_COMMIT();
    };

    float acc[4][4][4];
#pragma unroll
    for (int i = 0; i < 4; i++)
#pragma unroll
        for (int j = 0; j < 4; j++)
#pragma unroll
            for (int k = 0; k < 4; k++) acc[i][j][k] = 0.f;

    issue(0, 0);
    issue(1, 1);

    for (int kt = 0; kt < KT; kt++) {
        const int s = kt % 3;
        if (kt < KT - 1) CP_WAIT1(); else CP_WAIT0();
        __syncthreads();
        if (kt + 2 < KT) issue(kt + 2, (kt + 2) % 3);

        const uint32_t stB = sb + (uint32_t)(s * HGSTG);
#pragma unroll
        for (int ks = 0; ks < 2; ks++) {
            uint32_t a[4][4], b[4][2];
#pragma unroll
            for (int mt = 0; mt < 4; mt++) ldsm4(a[mt], stB + aoff[mt] + ks * 32);
#pragma unroll
            for (int p = 0; p < 2; p++) {
                uint32_t t[4];
                ldsm4(t, stB + boff[p] + ks * 32);
                b[2 * p][0] = t[0]; b[2 * p][1] = t[1];
                b[2 * p + 1][0] = t[2]; b[2 * p + 1][1] = t[3];
            }
#pragma unroll
            for (int mt = 0; mt < 4; mt++)
#pragma unroll
                for (int nt = 0; nt < 4; nt++)
                    mma_f16(acc[mt][nt], a[mt], b[nt]);
        }
    }

    __syncthreads();
    uint32_t* Cw = (uint32_t*)smem;
#pragma unroll
    for (int mt = 0; mt < 4; mt++)
#pragma unroll
        for (int h = 0; h < 2; h++) {
            int row = wm + mt * 16 + gid + h * 8;
#pragma unroll
            for (int nt = 0; nt < 4; nt++)
                Cw[row * (CSTR / 2) + wn / 2 + nt * 4 + tig] =
                    pack2(acc[mt][nt][h * 2], acc[mt][nt][h * 2 + 1]);
        }
    __syncthreads();

    const __half* Cs = (const __half*)smem;
    const int b = m0 >> 12;
    const int pix0 = m0 & 4095;
    const int pr0 = pix0 >> 7;

    if (n0 == 64) {
        __half* G = d_Gh + (long long)m0 * C8;
#pragma unroll
        for (int it = 0; it < 8; it++) {
            int idx = tid + it * 256;
            int row = idx >> 3, q = idx & 7;
            uint4 v = *reinterpret_cast<const uint4*>(&Cw[row * (CSTR / 2) + q * 4]);
            *reinterpret_cast<uint4*>(&G[row * C8 + q * 8]) = v;
        }
    } else if (n0 == 0) {
        __half* F = d_Fh + (b * NPOOL + pr0 * 32) * C8;
        const __half2* C2s = (const __half2*)Cs;
#pragma unroll
        for (int it = 0; it < 8; it++) {
            int idx = tid + it * 256;
            int p = idx >> 5, c2 = idx & 31;
            int base = ((p >> 5) * 2) * 64 + (p & 31) * 2;
            __half2 v0 = C2s[(base) * (CSTR / 2) + c2];
            __half2 v1 = C2s[(base + 1) * (CSTR / 2) + c2];
            __half2 v2 = C2s[(base + 64) * (CSTR / 2) + c2];
            __half2 v3 = C2s[(base + 65) * (CSTR / 2) + c2];
            __half2 v = __hmax2(__hmax2(v0, v1), __hmax2(v2, v3));
            *reinterpret_cast<__half2*>(&F[p * C8 + 2 * c2]) = v;
        }
    } else {
        int c = tid & 63;
        int pgrp = tid >> 6;
        int d = n0 - 128 + c;
        __half buf[16];
#pragma unroll
        for (int j = 0; j < 16; j++) {
            int p = pgrp * 16 + j;
            int base = ((p >> 5) * 2) * 64 + (p & 31) * 2;
            __half v0 = Cs[(base) * CSTR + c];
            __half v1 = Cs[(base + 1) * CSTR + c];
            __half v2 = Cs[(base + 64) * CSTR + c];
            __half v3 = Cs[(base + 65) * CSTR + c];
            buf[j] = __hmax(__hmax(v0, v1), __hmax(v2, v3));
        }
        __half* dst = d_Vth + ((long long)b * C2 + d) * NPOOL + pr0 * 32 + pgrp * 16;
        *reinterpret_cast<uint4*>(dst) = *reinterpret_cast<uint4*>(buf);
        *reinterpret_cast<uint4*>(dst + 8) = *reinterpret_cast<uint4*>(buf + 8);
    }
}

// ---------------------------------------------------------------------------
// Output GEMM: out = gamma * (Oh @ WoT^T) + x   (M=32768, N=512, K=256)
// ---------------------------------------------------------------------------
__global__ void __launch_bounds__(256, 2) gemm_out(
    const float* __restrict__ resid, const float* __restrict__ gamma,
    float* __restrict__ C)
{
    extern __shared__ __align__(16) char smem[];
    const int m0 = blockIdx.y * 256;
    const int n0 = blockIdx.x * 64;
    const int tid = threadIdx.x;
    const int wid = tid >> 5, lane = tid & 31;
    const int gid = lane >> 2, tig = lane & 3;
    const int wm = (wid & 3) * 64;
    const int wn = (wid >> 2) * 32;

    const __half* A = d_Oh;
    const __half* Bt = d_WoT;
    const uint32_t sb = smem_u32(smem);
    const int KT = C2 / 32;

    const int arow = lane & 15;
    const int acol = (lane >> 4) << 4;
    const int brow = (lane & 7) + ((lane >> 4) & 1) * 8;
    const int bcol = ((lane >> 3) & 1) << 4;
    uint32_t aoff[4], boff[2];
#pragma unroll
    for (int mt = 0; mt < 4; mt++) aoff[mt] = (uint32_t)((wm + mt * 16 + arow) * 80 + acol);
#pragma unroll
    for (int p = 0; p < 2; p++) boff[p] = (uint32_t)(HASTG + (wn + p * 16 + brow) * 80 + bcol);

    auto issue = [&](int kt, int s) {
        const uint32_t aB = sb + (uint32_t)(s * HGSTG);
        const uint32_t bB = aB + HASTG;
#pragma unroll
        for (int it = 0; it < 4; it++) {
            int idx = tid + it * 256;
            int r = idx >> 2, q = idx & 3;
            cp16(aB + (uint32_t)(r * 80 + q * 16),
                 A + (long long)(m0 + r) * C2 + kt * 32 + q * 8);
        }
        {
            int r = tid >> 2, q = tid & 3;
            cp16(bB + (uint32_t)(r * 80 + q * 16),
                 Bt + (long long)(n0 + r) * C2 + kt * 32 + q * 8);
        }
        CP_COMMIT();
    };

    float acc[4][4][4];
#pragma unroll
    for (int i = 0; i < 4; i++)
#pragma unroll
        for (int j = 0; j < 4; j++)
#pragma unroll
            for (int k = 0; k < 4; k++) acc[i][j][k] = 0.f;

    issue(0, 0);
    issue(1, 1);

    for (int kt = 0; kt < KT; kt++) {
        const int s = kt % 3;
        if (kt < KT - 1) CP_WAIT1(); else CP_WAIT0();
        __syncthreads();
        if (kt + 2 < KT) issue(kt + 2, (kt + 2) % 3);

        const uint32_t stB = sb + (uint32_t)(s * HGSTG);
#pragma unroll
        for (int ks = 0; ks < 2; ks++) {
            uint32_t a[4][4], b[4][2];
#pragma unroll
            for (int mt = 0; mt < 4; mt++) ldsm4(a[mt], stB + aoff[mt] + ks * 32);
#pragma unroll
            for (int p = 0; p < 2; p++) {
                uint32_t t[4];
                ldsm4(t, stB + boff[p] + ks * 32);
                b[2 * p][0] = t[0]; b[2 * p][1] = t[1];
                b[2 * p + 1][0] = t[2]; b[2 * p + 1][1] = t[3];
            }
#pragma unroll
            for (int mt = 0; mt < 4; mt++)
#pragma unroll
                for (int nt = 0; nt < 4; nt++)
                    mma_f16(acc[mt][nt], a[mt], b[nt]);
        }
    }

    const float gm = gamma[0];
#pragma unroll
    for (int mt = 0; mt < 4; mt++)
#pragma unroll
        for (int h = 0; h < 2; h++) {
            long long row = m0 + wm + mt * 16 + gid + h * 8;
#pragma unroll
            for (int nt = 0; nt < 4; nt++) {
                long long off = row * CC + n0 + wn + nt * 8 + 2 * tig;
                float2 rv = *reinterpret_cast<const float2*>(&resid[off]);
                float2 v;
                v.x = fmaf(gm, acc[mt][nt][h * 2], rv.x);
                v.y = fmaf(gm, acc[mt][nt][h * 2 + 1], rv.y);
                *reinterpret_cast<float2*>(&C[off]) = v;
            }
        }
}

// ---------------------------------------------------------------------------
// Warp-specialized flash attention: 384 thr / 64 q per CTA, 16 chunks of 64.
//   Warps 8-11 (producers): S = Q@K^T, warp-local softmax stats, P (fp16) +
//     per-row rescale factors into double-buffered smem.
//   Warps 0-7 (consumers): accO rescale + P@V (R12 PV shape, 16r x 128c).
// K on producer cp.async queue, V on consumer queue. Named barriers:
//   ready0/1 = 1/2 (S arrive -> PV sync), free0/1 = 3/4 (PV arrive -> S sync),
//   5 = S-group internal (128), 6 = PV-group internal (256).
// Smem 118 KB -> 1 CTA/SM.
// ---------------------------------------------------------------------------
#define FQ 64
#define NCHUNK 16
#define SM_Q 0
#define SM_K 9216
#define SM_V 27648
#define SM_P 101376
#define SM_SC 119808
#define SM_L 120320
#define FLASH_SMEM 120576

__global__ void __launch_bounds__(384, 1) flash_h()
{
    extern __shared__ __align__(16) char fsm[];
    const uint32_t sb = smem_u32(fsm);

    const int b = blockIdx.y;
    const int q0 = blockIdx.x * FQ;
    const __half* Qg = d_Gh + ((long long)b * NPIX + q0) * C8;
    const __half* Fb = d_Fh + b * NPOOL * C8;
    const __half* Vtb = d_Vth + (long long)b * C2 * NPOOL;
    __half* Ob = d_Oh + (long long)b * NPIX * C2;

    const int tid = threadIdx.x;
    const int wid = tid >> 5, lane = tid & 31;
    const int gid = lane >> 2, tig = lane & 3;
    const int arow = lane & 15;
    const int acol = (lane >> 4) << 4;
    const int brow = (lane & 7) + ((lane >> 4) & 1) * 8;
    const int bcol = ((lane >> 3) & 1) << 4;

    float* scbuf = (float*)(fsm + SM_SC);
    float* lbuf = (float*)(fsm + SM_L);

    if (wid >= 8) {
        // ================= PRODUCER: S warps (tid 256..383) =================
        const int st = tid - 256;            // 0..127
        const int wm = (wid - 8) * 16;       // 16 distinct rows per warp
        const uint32_t qoff = (uint32_t)(SM_Q + (wm + arow) * 144 + acol);
        uint32_t koff[4];
#pragma unroll
        for (int j = 0; j < 4; j++)
            koff[j] = (uint32_t)(SM_K + (j * 16 + brow) * 144 + bcol);

        auto issueK = [&](int c) {
            const uint32_t kb = sb + SM_K + (uint32_t)((c & 1) * 9216);
#pragma unroll
            for (int it = 0; it < 4; it++) {
                int idx = st + it * 128;
                int r = idx >> 3, q = idx & 7;
                cp16(kb + (uint32_t)(r * 144 + q * 16),
                     Fb + (c * 64 + r) * C8 + q * 8);
            }
            CP_COMMIT();
        };

        // prologue: Q + K0, one group
#pragma unroll
        for (int it = 0; it < 4; it++) {
            int idx = st + it * 128;
            int r = idx >> 3, q = idx & 7;
            cp16(sb + SM_Q + (uint32_t)(r * 144 + q * 16),
                 Qg + (long long)r * C8 + q * 8);
        }
        issueK(0);
        CP_WAIT0();
        bar_sync(5, 128);

        uint32_t qf[4][4];
#pragma unroll
        for (int ks = 0; ks < 4; ks++) ldsm4(qf[ks], sb + qoff + ks * 32);

        float mM[2] = {-1e30f, -1e30f};
        float lL[2] = {0.f, 0.f};

        for (int c = 0; c < NCHUNK; c++) {
            if (c) {
                CP_WAIT0();            // K(c) landed (this thread's parts)
                bar_sync(5, 128);      // all S threads' K parts visible;
                                       // all S warps done with prev chunk
            }
            if (c + 1 < NCHUNK) issueK(c + 1);

            const uint32_t sK = (uint32_t)((c & 1) * 9216);

            // ---- S = Q @ K^T : 16 rows x 64 keys ----
            float accS[8][4];
#pragma unroll
            for (int n = 0; n < 8; n++)
#pragma unroll
                for (int k = 0; k < 4; k++) accS[n][k] = 0.f;
#pragma unroll
            for (int ks = 0; ks < 4; ks++) {
#pragma unroll
                for (int j = 0; j < 4; j++) {
                    uint32_t t[4], b0[2], b1[2];
                    ldsm4(t, sb + sK + koff[j] + ks * 32);
                    b0[0] = t[0]; b0[1] = t[1];
                    b1[0] = t[2]; b1[1] = t[3];
                    mma_f16(accS[2 * j], qf[ks], b0);
                    mma_f16(accS[2 * j + 1], qf[ks], b1);
                }
            }

            // ---- warp-local row max ----
            float cl = -1e30f, ch = -1e30f;
#pragma unroll
            for (int nt = 0; nt < 8; nt++) {
                cl = fmaxf(cl, fmaxf(accS[nt][0], accS[nt][1]));
                ch = fmaxf(ch, fmaxf(accS[nt][2], accS[nt][3]));
            }
#pragma unroll
            for (int o = 1; o <= 2; o <<= 1) {
                cl = fmaxf(cl, __shfl_xor_sync(0xffffffffu, cl, o));
                ch = fmaxf(ch, __shfl_xor_sync(0xffffffffu, ch, o));
            }
            float mn0 = fmaxf(mM[0], cl);
            float mn1 = fmaxf(mM[1], ch);
            float sc0 = __expf(mM[0] - mn0);
            float sc1 = __expf(mM[1] - mn1);
            mM[0] = mn0;
            mM[1] = mn1;
            float nm0 = -mn0 * L2E, nm1 = -mn1 * L2E;

            // ---- P fp16 in registers + row sums ----
            uint32_t pf[4][4];
            float ps0 = 0.f, ps1 = 0.f;
#pragma unroll
            for (int ks = 0; ks < 4; ks++) {
                pf[ks][0] = ex2_h2(pack2(fmaf(accS[2 * ks][0], L2E, nm0),
                                         fmaf(accS[2 * ks][1], L2E, nm0)));
                pf[ks][1] = ex2_h2(pack2(fmaf(accS[2 * ks][2], L2E, nm1),
                                         fmaf(accS[2 * ks][3], L2E, nm1)));
                pf[ks][2] = ex2_h2(pack2(fmaf(accS[2 * ks + 1][0], L2E, nm0),
                                         fmaf(accS[2 * ks + 1][1], L2E, nm0)));
                pf[ks][3] = ex2_h2(pack2(fmaf(accS[2 * ks + 1][2], L2E, nm1),
                                         fmaf(accS[2 * ks + 1][3], L2E, nm1)));
                ps0 += h2sum(pf[ks][0]) + h2sum(pf[ks][2]);
                ps1 += h2sum(pf[ks][1]) + h2sum(pf[ks][3]);
            }
#pragma unroll
            for (int o = 1; o <= 2; o <<= 1) {
                ps0 += __shfl_xor_sync(0xffffffffu, ps0, o);
                ps1 += __shfl_xor_sync(0xffffffffu, ps1, o);
            }
            lL[0] = lL[0] * sc0 + ps0;
            lL[1] = lL[1] * sc1 + ps1;

            // ---- wait P-buffer free (consumers done with chunk c-2) ----
            if (c >= 2) bar_sync(3 + (c & 1), 384);

            // ---- publish P + sc ----
            uint32_t* Pw = (uint32_t*)(fsm + SM_P + (c & 1) * 9216);
            const int w0 = (wm + gid) * 36;
#pragma unroll
            for (int ks = 0; ks < 4; ks++) {
                Pw[w0 + 8 * ks + tig] = pf[ks][0];
                Pw[w0 + 8 * 36 + 8 * ks + tig] = pf[ks][1];
                Pw[w0 + 8 * ks + 4 + tig] = pf[ks][2];
                Pw[w0 + 8 * 36 + 8 * ks + 4 + tig] = pf[ks][3];
            }
            if (tig == 0) {
                float* scb = scbuf + (c & 1) * 64;
                scb[wm + gid] = sc0;
                scb[wm + gid + 8] = sc1;
            }
            MEMBAR_CTA();
            bar_arrive(1 + (c & 1), 384);
        }
        // publish normalizers
        if (tig == 0) {
            lbuf[wm + gid] = lL[0];
            lbuf[wm + gid + 8] = lL[1];
        }
    } else {
        // ================= CONSUMER: PV warps (tid 0..255) =================
        const int wm = (wid & 3) * 16;
        const int wgrp = wid >> 2;
        const int wnP = wgrp * 128;
        const uint32_t poff = (uint32_t)(SM_P + (wm + arow) * 144 + acol);
        uint32_t voff[8];
#pragma unroll
        for (int p = 0; p < 8; p++)
            voff[p] = (uint32_t)(SM_V + (wnP + p * 16 + brow) * 144 + bcol);

        auto issueV = [&](int c) {
            const uint32_t vb = sb + SM_V + (uint32_t)((c & 1) * 36864);
#pragma unroll
            for (int it = 0; it < 8; it++) {
                int idx = tid + it * 256;
                int r = idx >> 3, q = idx & 7;
                cp16(vb + (uint32_t)(r * 144 + q * 16),
                     Vtb + (long long)r * NPOOL + c * 64 + q * 8);
            }
            CP_COMMIT();
        };

        issueV(0);

        float accO[16][4];
#pragma unroll
        for (int n = 0; n < 16; n++)
#pragma unroll
            for (int k = 0; k < 4; k++) accO[n][k] = 0.f;

        for (int c = 0; c < NCHUNK; c++) {
            bar_sync(1 + (c & 1), 384);    // P(c)+sc(c) ready; all PV past c-1
            if (c + 1 < NCHUNK) issueV(c + 1);
            if (c + 1 < NCHUNK) CP_WAIT1(); else CP_WAIT0();  // V(c) landed
            bar_sync(6, 256);              // all PV threads' V parts visible

            const uint32_t sP = (uint32_t)((c & 1) * 9216);
            const uint32_t sV = (uint32_t)((c & 1) * 36864);
            const float* scb = scbuf + (c & 1) * 64;
            float sc0 = scb[wm + gid];
            float sc1 = scb[wm + gid + 8];
#pragma unroll
            for (int nt = 0; nt < 16; nt++) {
                accO[nt][0] *= sc0;
                accO[nt][1] *= sc0;
                accO[nt][2] *= sc1;
                accO[nt][3] *= sc1;
            }

#pragma unroll
            for (int ks = 0; ks < 4; ks++) {
                uint32_t a[4];
                ldsm4(a, sb + sP + poff + ks * 32);
#pragma unroll
                for (int p = 0; p < 8; p++) {
                    uint32_t t[4], b0[2], b1[2];
                    ldsm4(t, sb + sV + voff[p] + ks * 32);
                    b0[0] = t[0]; b0[1] = t[1];
                    b1[0] = t[2]; b1[1] = t[3];
                    mma_f16(accO[2 * p], a, b0);
                    mma_f16(accO[2 * p + 1], a, b1);
                }
            }
            bar_arrive(3 + (c & 1), 384);  // P-buffer free
        }
    }

    __syncthreads();   // l values published

    if (wid < 8) {
        const int wm = (wid & 3) * 16;
        const int wgrp = wid >> 2;
        const int wnP = wgrp * 128;
        // reload accO? no — accO lives in this scope only for wid<8 branch.
        // NOTE: accO is out of scope here; epilogue must be inside the branch.
    }
    // (epilogue handled inside consumer branch via lbuf after barrier below)
}

// ---------------------------------------------------------------------------
// x -> fp16
// ---------------------------------------------------------------------------
__global__ void convert_x_kernel(const float* __restrict__ x)
{
    int idx = blockIdx.x * blockDim.x + threadIdx.x;
    const float4 v = reinterpret_cast<const float4*>(x)[idx];
    uint2 u;
    u.x = pack2(v.x, v.y);
    u.y = pack2(v.z, v.w);
    reinterpret_cast<uint2*>(d_Xh)[idx] = u;
}

// ---------------------------------------------------------------------------
// Weights: WcatT [384][512] fp16, WoT [512][256] fp16
// ---------------------------------------------------------------------------
__global__ void concat_w_kernel(const float* __restrict__ wf,
                                const float* __restrict__ wg,
                                const float* __restrict__ wh,
                                const float* __restrict__ wo)
{
    int idx = blockIdx.x * blockDim.x + threadIdx.x;
    const int n1 = NCAT * CC;
    if (idx < n1) {
        int j = idx / CC, k = idx % CC;
        float v;
        if (j < 64)       v = wf[k * C8 + j];
        else if (j < 128) v = wg[k * C8 + (j - 64)];
        else              v = wh[k * C2 + (j - 128)];
        d_WcatT[idx] = __float2half_rn(v);
    } else if (idx < n1 + CC * C2) {
        int i2 = idx - n1;
        int c = i2 / C2, d = i2 % C2;
        d_WoT[i2] = __float2half_rn(wo[d * CC + c]);
    }
}

// ---------------------------------------------------------------------------
// Launch
// ---------------------------------------------------------------------------
extern "C" void kernel_launch(void* const* d_in, const int* in_sizes, int n_in,
                              void* d_out, int out_size);

// -- NOTE: the epilogue scoping issue above is fixed by restructuring the
//    consumer branch to include normalization + store after an in-branch
//    wait on lbuf via named barrier 7. Redefine flash here properly. --

// Corrected flash kernel (the one actually launched):
__global__ void __launch_bounds__(384, 1) flash_ws()
{
    extern __shared__ __align__(16) char fsm[];
    const uint32_t sb = smem_u32(fsm);

    const int b = blockIdx.y;
    const int q0 = blockIdx.x * FQ;
    const __half* Qg = d_Gh + ((long long)b * NPIX + q0) * C8;
    const __half* Fb = d_Fh + b * NPOOL * C8;
    const __half* Vtb = d_Vth + (long long)b * C2 * NPOOL;
    __half* Ob = d_Oh + (long long)b * NPIX * C2;

    const int tid = threadIdx.x;
    const int wid = tid >> 5, lane = tid & 31;
    const int gid = lane >> 2, tig = lane & 3;
    const int arow = lane & 15;
    const int acol = (lane >> 4) << 4;
    const int brow = (lane & 7) + ((lane >> 4) & 1) * 8;
    const int bcol = ((lane >> 3) & 1) << 4;

    float* scbuf = (float*)(fsm + SM_SC);
    float* lbuf = (float*)(fsm + SM_L);

    if (wid >= 8) {
        const int st = tid - 256;
        const int wm = (wid - 8) * 16;
        const uint32_t qoff = (uint32_t)(SM_Q + (wm + arow) * 144 + acol);
        uint32_t koff[4];
#pragma unroll
        for (int j = 0; j < 4; j++)
            koff[j] = (uint32_t)(SM_K + (j * 16 + brow) * 144 + bcol);

        auto issueK = [&](int c) {
            const uint32_t kb = sb + SM_K + (uint32_t)((c & 1) * 9216);
#pragma unroll
            for (int it = 0; it < 4; it++) {
                int idx = st + it * 128;
                int r = idx >> 3, q = idx & 7;
                cp16(kb + (uint32_t)(r * 144 + q * 16),
                     Fb + (c * 64 + r) * C8 + q * 8);
            }
            CP_COMMIT();
        };

#pragma unroll
        for (int it = 0; it < 4; it++) {
            int idx = st + it * 128;
            int r = idx >> 3, q = idx & 7;
            cp16(sb + SM_Q + (uint32_t)(r * 144 + q * 16),
                 Qg + (long long)r * C8 + q * 8);
        }
        issueK(0);
        CP_WAIT0();
        bar_sync(5, 128);

        uint32_t qf[4][4];
#pragma unroll
        for (int ks = 0; ks < 4; ks++) ldsm4(qf[ks], sb + qoff + ks * 32);

        float mM[2] = {-1e30f, -1e30f};
        float lL[2] = {0.f, 0.f};

        for (int c = 0; c < NCHUNK; c++) {
            if (c) {
                CP_WAIT0();
                bar_sync(5, 128);
            }
            if (c + 1 < NCHUNK) issueK(c + 1);

            const uint32_t sK = (uint32_t)((c & 1) * 9216);
            float accS[8][4];
#pragma unroll
            for (int n = 0; n < 8; n++)
#pragma unroll
                for (int k = 0; k < 4; k++) accS[n][k] = 0.f;
#pragma unroll
            for (int ks = 0; ks < 4; ks++) {
#pragma unroll
                for (int j = 0; j < 4; j++) {
                    uint32_t t[4], b0[2], b1[2];
                    ldsm4(t, sb + sK + koff[j] + ks * 32);
                    b0[0] = t[0]; b0[1] = t[1];
                    b1[0] = t[2]; b1[1] = t[3];
                    mma_f16(accS[2 * j], qf[ks], b0);
                    mma_f16(accS[2 * j + 1], qf[ks], b1);
                }
            }

            float cl = -1e30f, ch = -1e30f;
#pragma unroll
            for (int nt = 0; nt < 8; nt++) {
                cl = fmaxf(cl, fmaxf(accS[nt][0], accS[nt][1]));
                ch = fmaxf(ch, fmaxf(accS[nt][2], accS[nt][3]));
            }
#pragma unroll
            for (int o = 1; o <= 2; o <<= 1) {
                cl = fmaxf(cl, __shfl_xor_sync(0xffffffffu, cl, o));
                ch = fmaxf(ch, __shfl_xor_sync(0xffffffffu, ch, o));
            }
            float mn0 = fmaxf(mM[0], cl);
            float mn1 = fmaxf(mM[1], ch);
            float sc0 = __expf(mM[0] - mn0);
            float sc1 = __expf(mM[1] - mn1);
            mM[0] = mn0;
            mM[1] = mn1;
            float nm0 = -mn0 * L2E, nm1 = -mn1 * L2E;

            uint32_t pf[4][4];
            float ps0 = 0.f, ps1 = 0.f;
#pragma unroll
            for (int ks = 0; ks < 4; ks++) {
                pf[ks][0] = ex2_h2(pack2(fmaf(accS[2 * ks][0], L2E, nm0),
                                         fmaf(accS[2 * ks][1], L2E, nm0)));
                pf[ks][1] = ex2_h2(pack2(fmaf(accS[2 * ks][2], L2E, nm1),
                                         fmaf(accS[2 * ks][3], L2E, nm1)));
                pf[ks][2] = ex2_h2(pack2(fmaf(accS[2 * ks + 1][0], L2E, nm0),
                                         fmaf(accS[2 * ks + 1][1], L2E, nm0)));
                pf[ks][3] = ex2_h2(pack2(fmaf(accS[2 * ks + 1][2], L2E, nm1),
                                         fmaf(accS[2 * ks + 1][3], L2E, nm1)));
                ps0 += h2sum(pf[ks][0]) + h2sum(pf[ks][2]);
                ps1 += h2sum(pf[ks][1]) + h2sum(pf[ks][3]);
            }
#pragma unroll
            for (int o = 1; o <= 2; o <<= 1) {
                ps0 += __shfl_xor_sync(0xffffffffu, ps0, o);
                ps1 += __shfl_xor_sync(0xffffffffu, ps1, o);
            }
            lL[0] = lL[0] * sc0 + ps0;
            lL[1] = lL[1] * sc1 + ps1;

            if (c >= 2) bar_sync(3 + (c & 1), 384);

            uint32_t* Pw = (uint32_t*)(fsm + SM_P + (c & 1) * 9216);
            const int w0 = (wm + gid) * 36;
#pragma unroll
            for (int ks = 0; ks < 4; ks++) {
                Pw[w0 + 8 * ks + tig] = pf[ks][0];
                Pw[w0 + 8 * 36 + 8 * ks + tig] = pf[ks][1];
                Pw[w0 + 8 * ks + 4 + tig] = pf[ks][2];
                Pw[w0 + 8 * 36 + 8 * ks + 4 + tig] = pf[ks][3];
            }
            if (tig == 0) {
                float* scb = scbuf + (c & 1) * 64;
                scb[wm + gid] = sc0;
                scb[wm + gid + 8] = sc1;
            }
            MEMBAR_CTA();
            bar_arrive(1 + (c & 1), 384);
        }
        if (tig == 0) {
            lbuf[wm + gid] = lL[0];
            lbuf[wm + gid + 8] = lL[1];
        }
        MEMBAR_CTA();
        bar_arrive(7, 384);            // l published
    } else {
        const int wm = (wid & 3) * 16;
        const int wgrp = wid >> 2;
        const int wnP = wgrp * 128;
        const uint32_t poff = (uint32_t)(SM_P + (wm + arow) * 144 + acol);
        uint32_t voff[8];
#pragma unroll
        for (int p = 0; p < 8; p++)
            voff[p] = (uint32_t)(SM_V + (wnP + p * 16 + brow) * 144 + bcol);

        auto issueV = [&](int c) {
            const uint32_t vb = sb + SM_V + (uint32_t)((c & 1) * 36864);
#pragma unroll
            for (int it = 0; it < 8; it++) {
                int idx = tid + it * 256;
                int r = idx >> 3, q = idx & 7;
                cp16(vb + (uint32_t)(r * 144 + q * 16),
                     Vtb + (long long)r * NPOOL + c * 64 + q * 8);
            }
            CP_COMMIT();
        };

        issueV(0);

        float accO[16][4];
#pragma unroll
        for (int n = 0; n < 16; n++)
#pragma unroll
            for (int k = 0; k < 4; k++) accO[n][k] = 0.f;

        for (int c = 0; c < NCHUNK; c++) {
            bar_sync(1 + (c & 1), 384);
            if (c + 1 < NCHUNK) issueV(c + 1);
            if (c + 1 < NCHUNK) CP_WAIT1(); else CP_WAIT0();
            bar_sync(6, 256);

            const uint32_t sP = (uint32_t)((c & 1) * 9216);
            const uint32_t sV = (uint32_t)((c & 1) * 36864);
            const float* scb = scbuf + (c & 1) * 64;
            float sc0 = scb[wm + gid];
            float sc1 = scb[wm + gid + 8];
#pragma unroll
            for (int nt = 0; nt < 16; nt++) {
                accO[nt][0] *= sc0;
                accO[nt][1] *= sc0;
                accO[nt][2] *= sc1;
                accO[nt][3] *= sc1;
            }
#pragma unroll
            for (int ks = 0; ks < 4; ks++) {
                uint32_t a[4];
                ldsm4(a, sb + sP + poff + ks * 32);
#pragma unroll
                for (int p = 0; p < 8; p++) {
                    uint32_t t[4], b0[2], b1[2];
                    ldsm4(t, sb + sV + voff[p] + ks * 32);
                    b0[0] = t[0]; b0[1] = t[1];
                    b1[0] = t[2]; b1[1] = t[3];
                    mma_f16(accO[2 * p], a, b0);
                    mma_f16(accO[2 * p + 1], a, b1);
                }
            }
            bar_arrive(3 + (c & 1), 384);
        }

        bar_sync(7, 384);              // wait l
        float il = 1.f / lbuf[wm + gid];
        float ih = 1.f / lbuf[wm + gid + 8];
        int row = q0 + wm + gid;
#pragma unroll
        for (int nt = 0; nt < 16; nt++) {
            int col = wnP + nt * 8 + 2 * tig;
            *reinterpret_cast<uint32_t*>(&Ob[(long long)row * C2 + col]) =
                pack2(accO[nt][0] * il, accO[nt][1] * il);
            *reinterpret_cast<uint32_t*>(&Ob[(long long)(row + 8) * C2 + col]) =
                pack2(accO[nt][2] * ih, accO[nt][3] * ih);
        }
    }
}

extern "C" void kernel_launch(void* const* d_in, const int* in_sizes, int n_in,
                              void* d_out, int out_size)
{
    const float* x     = (const float*)d_in[0];
    const float* wf    = (const float*)d_in[1];
    const float* wg    = (const float*)d_in[2];
    const float* wh    = (const float*)d_in[3];
    const float* wo    = (const float*)d_in[4];
    const float* gamma = (const float*)d_in[5];
    float* out = (float*)d_out;

    cudaFuncSetAttribute(gemm_proj,
                         cudaFuncAttributeMaxDynamicSharedMemorySize, SMEM_TOTAL_G);
    cudaFuncSetAttribute(gemm_out,
                         cudaFuncAttributeMaxDynamicSharedMemorySize, SMEM_TOTAL_G);
    cudaFuncSetAttribute(flash_ws,
                         cudaFuncAttributeMaxDynamicSharedMemorySize, FLASH_SMEM);

    // 0) x -> fp16
    convert_x_kernel<<<(BATCH * NPIX * CC / 4 + 255) / 256, 256>>>(x);

    // 1) weights -> fp16 transposed
    concat_w_kernel<<<(NCAT * CC + CC * C2 + 255) / 256, 256>>>(wf, wg, wh, wo);

    // 2+3) projection GEMM with fused pooling epilogue
    gemm_proj<<<dim3(NCAT / 64, (BATCH * NPIX) / 256), 256, SMEM_TOTAL_G>>>();

    // 4-6) warp-specialized fused attention -> Oh fp16
    flash_ws<<<dim3(NPIX / FQ, BATCH), 384, FLASH_SMEM>>>();

    // 7) out = gamma * (Oh @ wo) + x
    gemm_out<<<dim3(CC / 64, (BATCH * NPIX) / 256), 256, SMEM_TOTAL_G>>>(x, gamma, out);
}